// round 1
// baseline (speedup 1.0000x reference)
#include <cuda_runtime.h>
#include <cuda_bf16.h>
#include <mma.h>
#include <math.h>

using namespace nvcuda;

#define NROWS 8192
#define DIM   512
#define TOPK  12
#define THETA 10.0f

// Scratch (device globals: allocation-free per harness rules)
__device__ __nv_bfloat16 g_hn[NROWS * DIM];            // 8 MB, normalized rows in bf16
__device__ float g_sim[(size_t)NROWS * NROWS];         // 256 MB similarity matrix

// ---------------------------------------------------------------------------
// Kernel 1: row L2 norms -> normalized bf16 rows
// one block per row, 256 threads, 2 elements/thread
// ---------------------------------------------------------------------------
__global__ __launch_bounds__(256) void norm_kernel(const float* __restrict__ h) {
    int row = blockIdx.x;
    int tid = threadIdx.x;
    const float* hr = h + (size_t)row * DIM;

    float v0 = hr[tid];
    float v1 = hr[tid + 256];
    float s = v0 * v0 + v1 * v1;

    // warp reduce
    #pragma unroll
    for (int off = 16; off > 0; off >>= 1)
        s += __shfl_xor_sync(0xFFFFFFFFu, s, off);

    __shared__ float red[8];
    if ((tid & 31) == 0) red[tid >> 5] = s;
    __syncthreads();
    if (tid < 32) {
        float t = (tid < 8) ? red[tid] : 0.0f;
        #pragma unroll
        for (int off = 4; off > 0; off >>= 1)
            t += __shfl_xor_sync(0xFFFFFFFFu, t, off);
        if (tid == 0) red[0] = t;
    }
    __syncthreads();

    float norm = sqrtf(red[0]);
    float inv = 1.0f / fmaxf(norm, 1e-8f);

    g_hn[(size_t)row * DIM + tid]       = __float2bfloat16(v0 * inv);
    g_hn[(size_t)row * DIM + tid + 256] = __float2bfloat16(v1 * inv);
}

// ---------------------------------------------------------------------------
// Kernel 2: Sim = hn @ hn^T  via wmma bf16 (fp32 accum)
// BM=BN=128, BK=16. 256 threads = 8 warps in 2x4; each warp: 64x32 (4x2 frags)
// ---------------------------------------------------------------------------
#define BM 128
#define BN 128
#define BK 16
#define SPAD 24   // smem row stride (elements), multiple of 8 for wmma ldm

__global__ __launch_bounds__(256) void gemm_kernel() {
    __shared__ __nv_bfloat16 sA[BM][SPAD];
    __shared__ __nv_bfloat16 sB[BN][SPAD];

    int bm = blockIdx.y * BM;
    int bn = blockIdx.x * BN;
    int tid = threadIdx.x;
    int wid = tid >> 5;
    int warpM = wid >> 2;      // 0..1  -> 64 rows each
    int warpN = wid & 3;       // 0..3  -> 32 cols each

    wmma::fragment<wmma::accumulator, 16, 16, 16, float> acc[4][2];
    #pragma unroll
    for (int i = 0; i < 4; i++)
        #pragma unroll
        for (int j = 0; j < 2; j++)
            wmma::fill_fragment(acc[i][j], 0.0f);

    // cooperative tile load: each thread loads one uint4 (8 bf16) per tile
    int lr = tid >> 1;             // 0..127
    int lc = (tid & 1) * 8;        // 0 or 8
    const __nv_bfloat16* gA = g_hn + (size_t)(bm + lr) * DIM + lc;
    const __nv_bfloat16* gB = g_hn + (size_t)(bn + lr) * DIM + lc;

    for (int k0 = 0; k0 < DIM; k0 += BK) {
        *reinterpret_cast<uint4*>(&sA[lr][lc]) =
            *reinterpret_cast<const uint4*>(gA + k0);
        *reinterpret_cast<uint4*>(&sB[lr][lc]) =
            *reinterpret_cast<const uint4*>(gB + k0);
        __syncthreads();

        wmma::fragment<wmma::matrix_a, 16, 16, 16, __nv_bfloat16, wmma::row_major> af[4];
        wmma::fragment<wmma::matrix_b, 16, 16, 16, __nv_bfloat16, wmma::col_major> bf[2];
        #pragma unroll
        for (int i = 0; i < 4; i++)
            wmma::load_matrix_sync(af[i], &sA[warpM * 64 + i * 16][0], SPAD);
        #pragma unroll
        for (int j = 0; j < 2; j++)
            wmma::load_matrix_sync(bf[j], &sB[warpN * 32 + j * 16][0], SPAD);

        #pragma unroll
        for (int i = 0; i < 4; i++)
            #pragma unroll
            for (int j = 0; j < 2; j++)
                wmma::mma_sync(acc[i][j], af[i], bf[j], acc[i][j]);

        __syncthreads();
    }

    #pragma unroll
    for (int i = 0; i < 4; i++)
        #pragma unroll
        for (int j = 0; j < 2; j++) {
            size_t r = bm + warpM * 64 + i * 16;
            size_t c = bn + warpN * 32 + j * 16;
            wmma::store_matrix_sync(&g_sim[r * NROWS + c], acc[i][j],
                                    NROWS, wmma::mem_row_major);
        }
}

// ---------------------------------------------------------------------------
// Kernel 3: per-row top-12 -> softmax(theta) -> gather-weighted sum of h
// one block per row, 256 threads
// ---------------------------------------------------------------------------
__global__ __launch_bounds__(256) void topk_kernel(const float* __restrict__ h,
                                                   float* __restrict__ out) {
    int row = blockIdx.x;
    int tid = threadIdx.x;
    const float* sim = g_sim + (size_t)row * NROWS;

    float v[TOPK];
    int   ix[TOPK];
    #pragma unroll
    for (int k = 0; k < TOPK; k++) { v[k] = -INFINITY; ix[k] = 0x7FFFFFFF; }

    // each thread scans 32 values as 8 float4s, coalesced across threads
    #pragma unroll
    for (int t = 0; t < 8; t++) {
        int base4 = t * 256 + tid;         // float4 index
        float4 q = reinterpret_cast<const float4*>(sim)[base4];
        int j0 = base4 * 4;
        float qq[4] = {q.x, q.y, q.z, q.w};
        #pragma unroll
        for (int e = 0; e < 4; e++) {
            float val = qq[e];
            if (val > v[TOPK - 1]) {
                int p = TOPK - 1;
                #pragma unroll
                for (int s = TOPK - 1; s > 0; s--) {
                    if (v[s - 1] < val) { v[s] = v[s - 1]; ix[s] = ix[s - 1]; p = s - 1; }
                }
                v[p] = val; ix[p] = j0 + e;
            }
        }
    }

    // shared merge: 256 sorted lists -> 1
    __shared__ float sV[256][TOPK];
    __shared__ int   sI[256][TOPK];
    #pragma unroll
    for (int k = 0; k < TOPK; k++) { sV[tid][k] = v[k]; sI[tid][k] = ix[k]; }

    for (int stride = 128; stride > 0; stride >>= 1) {
        __syncthreads();
        if (tid < stride) {
            float mv[TOPK]; int mi[TOPK];
            int a = 0, b = 0;
            #pragma unroll
            for (int k = 0; k < TOPK; k++) {
                float va = sV[tid][a],          vb = sV[tid + stride][b];
                int   ia = sI[tid][a],          ib = sI[tid + stride][b];
                bool takeA = (va > vb) || (va == vb && ia < ib);
                if (takeA) { mv[k] = va; mi[k] = ia; a++; }
                else       { mv[k] = vb; mi[k] = ib; b++; }
            }
            #pragma unroll
            for (int k = 0; k < TOPK; k++) { sV[tid][k] = mv[k]; sI[tid][k] = mi[k]; }
        }
    }
    __syncthreads();

    __shared__ float sBeta[TOPK];
    __shared__ int   sIdx[TOPK];
    if (tid == 0) {
        float m = sV[0][0];           // sorted desc -> max first
        float e[TOPK], sum = 0.0f;
        #pragma unroll
        for (int k = 0; k < TOPK; k++) {
            e[k] = expf(THETA * (sV[0][k] - m));
            sum += e[k];
        }
        float inv = 1.0f / sum;
        #pragma unroll
        for (int k = 0; k < TOPK; k++) { sBeta[k] = e[k] * inv; sIdx[k] = sI[0][k]; }
    }
    __syncthreads();

    float beta[TOPK];
    const float* hp[TOPK];
    #pragma unroll
    for (int k = 0; k < TOPK; k++) {
        beta[k] = sBeta[k];
        hp[k] = h + (size_t)sIdx[k] * DIM;
    }

    #pragma unroll
    for (int d = tid; d < DIM; d += 256) {
        float acc = 0.0f;
        #pragma unroll
        for (int k = 0; k < TOPK; k++)
            acc += beta[k] * hp[k][d];
        out[(size_t)row * DIM + d] = acc;
    }
}

// ---------------------------------------------------------------------------
extern "C" void kernel_launch(void* const* d_in, const int* in_sizes, int n_in,
                              void* d_out, int out_size) {
    const float* h = (const float*)d_in[0];
    float* out = (float*)d_out;

    norm_kernel<<<NROWS, 256>>>(h);
    gemm_kernel<<<dim3(NROWS / BN, NROWS / BM), 256>>>();
    topk_kernel<<<NROWS, 256>>>(h, out);
}

// round 4
// speedup vs baseline: 1.4527x; 1.4527x over previous
#include <cuda_runtime.h>
#include <cuda_bf16.h>
#include <math.h>
#include <cstdint>

#define NROWS 8192
#define DIM   512
#define TOPK  12
#define THETA 10.0f

// ---------------- device scratch (no allocation allowed) -------------------
__device__ __nv_bfloat16 g_hn[NROWS * DIM];            // 8 MB normalized bf16
__device__ float g_sim[(size_t)NROWS * NROWS];         // 256 MB similarity

__device__ __forceinline__ uint32_t smem_u32(const void* p) {
    uint32_t a;
    asm("{ .reg .u64 t; cvta.to.shared.u64 t, %1; cvt.u32.u64 %0, t; }"
        : "=r"(a) : "l"(p));
    return a;
}
__device__ __forceinline__ void cp_async16(uint32_t dst, const void* src) {
    asm volatile("cp.async.cg.shared.global [%0], [%1], 16;" :: "r"(dst), "l"(src));
}
__device__ __forceinline__ void cp_commit() {
    asm volatile("cp.async.commit_group;" ::: "memory");
}
template <int N>
__device__ __forceinline__ void cp_wait() {
    asm volatile("cp.async.wait_group %0;" :: "n"(N) : "memory");
}
__device__ __forceinline__ void ldsm_x4(uint32_t* r, uint32_t addr) {
    asm volatile("ldmatrix.sync.aligned.m8n8.x4.shared.b16 {%0,%1,%2,%3}, [%4];"
                 : "=r"(r[0]), "=r"(r[1]), "=r"(r[2]), "=r"(r[3]) : "r"(addr));
}
__device__ __forceinline__ void mma16816(float* c, const uint32_t* a,
                                         uint32_t b0, uint32_t b1) {
    asm volatile(
        "mma.sync.aligned.m16n8k16.row.col.f32.bf16.bf16.f32 "
        "{%0,%1,%2,%3}, {%4,%5,%6,%7}, {%8,%9}, {%0,%1,%2,%3};"
        : "+f"(c[0]), "+f"(c[1]), "+f"(c[2]), "+f"(c[3])
        : "r"(a[0]), "r"(a[1]), "r"(a[2]), "r"(a[3]), "r"(b0), "r"(b1));
}

// ---------------------------------------------------------------------------
// Kernel 1: row L2 norms -> normalized bf16 rows
// ---------------------------------------------------------------------------
__global__ __launch_bounds__(256) void norm_kernel(const float* __restrict__ h) {
    int row = blockIdx.x;
    int tid = threadIdx.x;
    const float* hr = h + (size_t)row * DIM;

    float v0 = hr[tid];
    float v1 = hr[tid + 256];
    float s = v0 * v0 + v1 * v1;
    #pragma unroll
    for (int off = 16; off > 0; off >>= 1) s += __shfl_xor_sync(~0u, s, off);

    __shared__ float red[8];
    if ((tid & 31) == 0) red[tid >> 5] = s;
    __syncthreads();
    if (tid < 32) {
        float t = (tid < 8) ? red[tid] : 0.0f;
        #pragma unroll
        for (int off = 4; off > 0; off >>= 1) t += __shfl_xor_sync(~0u, t, off);
        if (tid == 0) red[0] = t;
    }
    __syncthreads();
    float inv = 1.0f / fmaxf(sqrtf(red[0]), 1e-8f);
    g_hn[(size_t)row * DIM + tid]       = __float2bfloat16(v0 * inv);
    g_hn[(size_t)row * DIM + tid + 256] = __float2bfloat16(v1 * inv);
}

// ---------------------------------------------------------------------------
// Kernel 2: Sim = hn @ hn^T, upper-triangular tiles only (symmetric), HMMA
//   BM=BN=128, BK=32, 3-stage cp.async pipeline, ldmatrix + mma.sync bf16
//   8 warps (2x4): each computes 64x32 via 4x4 m16n8k16 fragments
// ---------------------------------------------------------------------------
#define BKC 32                       // K per stage (bf16 elems)
#define NITER (DIM / BKC)            // 16
#define ROWB 80                      // smem row stride in bytes (64B data + 16B pad)
#define STAGE_BYTES (2 * 128 * ROWB) // A + B per stage = 20480
#define GSMEM (3 * STAGE_BYTES)      // 61440

__device__ __forceinline__ void load_stage(uint32_t sbase, int buf, int c,
                                           int tid, int bm, int bn) {
    uint32_t sA = sbase + buf * STAGE_BYTES;
    uint32_t sB = sA + 128 * ROWB;
    const char* gb = (const char*)g_hn;
    #pragma unroll
    for (int p = 0; p < 2; p++) {
        int i = tid + p * 256;
        int row = i >> 2, seg = i & 3;
        size_t koff = (size_t)c * BKC + seg * 8;           // bf16 elements
        cp_async16(sA + row * ROWB + seg * 16,
                   gb + ((size_t)(bm + row) * DIM + koff) * 2);
        cp_async16(sB + row * ROWB + seg * 16,
                   gb + ((size_t)(bn + row) * DIM + koff) * 2);
    }
}

__global__ __launch_bounds__(256) void gemm_kernel() {
    const int I = blockIdx.y, J = blockIdx.x;
    if (J < I) return;                       // symmetric: upper triangle only
    const int bm = I * 128, bn = J * 128;

    extern __shared__ char smem[];
    const uint32_t sbase = smem_u32(smem);
    const int tid = threadIdx.x;
    const int lane = tid & 31;
    const int wid = tid >> 5;
    const int warpM = wid >> 2;              // 0..1 -> 64 rows
    const int warpN = wid & 3;               // 0..3 -> 32 cols

    float acc[4][4][4];
    #pragma unroll
    for (int mi = 0; mi < 4; mi++)
        #pragma unroll
        for (int ni = 0; ni < 4; ni++)
            #pragma unroll
            for (int q = 0; q < 4; q++) acc[mi][ni][q] = 0.0f;

    load_stage(sbase, 0, 0, tid, bm, bn); cp_commit();
    load_stage(sbase, 1, 1, tid, bm, bn); cp_commit();

    // per-warp ldmatrix base addresses (lane-dependent)
    const uint32_t aLane = (uint32_t)((warpM * 64 + (lane & 15)) * ROWB + (lane >> 4) * 16);
    const uint32_t bLane = (uint32_t)(128 * ROWB + (warpN * 32 + (lane & 15)) * ROWB + (lane >> 4) * 16);

    for (int c = 0; c < NITER; c++) {
        if (c + 2 < NITER) cp_wait<1>(); else cp_wait<0>();
        __syncthreads();
        if (c + 2 < NITER) load_stage(sbase, (c + 2) % 3, c + 2, tid, bm, bn);
        cp_commit();

        const uint32_t sbuf = sbase + (c % 3) * STAGE_BYTES;
        #pragma unroll
        for (int ks = 0; ks < 2; ks++) {
            uint32_t a[4][4], b[2][4];
            #pragma unroll
            for (int mi = 0; mi < 4; mi++)
                ldsm_x4(a[mi], sbuf + aLane + mi * (16 * ROWB) + ks * 32);
            #pragma unroll
            for (int nj = 0; nj < 2; nj++)
                ldsm_x4(b[nj], sbuf + bLane + nj * (16 * ROWB) + ks * 32);
            #pragma unroll
            for (int mi = 0; mi < 4; mi++)
                #pragma unroll
                for (int ni = 0; ni < 4; ni++) {
                    const int nj = ni >> 1, hi = ni & 1;
                    mma16816(acc[mi][ni], a[mi], b[nj][hi ? 1 : 0], b[nj][hi ? 3 : 2]);
                }
        }
    }

    // epilogue: normal tile store + transposed store for off-diagonal tiles
    const int r0 = bm + warpM * 64 + (lane >> 2);
    const int c0 = bn + warpN * 32 + (lane & 3) * 2;
    const bool offdiag = (I != J);
    #pragma unroll
    for (int mi = 0; mi < 4; mi++) {
        #pragma unroll
        for (int ni = 0; ni < 4; ni++) {
            const int r = r0 + mi * 16;
            const int cc = c0 + ni * 8;
            float* p0 = g_sim + (size_t)r * NROWS + cc;
            float* p1 = g_sim + (size_t)(r + 8) * NROWS + cc;
            p0[0] = acc[mi][ni][0]; p0[1] = acc[mi][ni][1];
            p1[0] = acc[mi][ni][2]; p1[1] = acc[mi][ni][3];
            if (offdiag) {
                float* q0 = g_sim + (size_t)cc * NROWS + r;
                float* q1 = g_sim + (size_t)(cc + 1) * NROWS + r;
                q0[0] = acc[mi][ni][0]; q1[0] = acc[mi][ni][1];
                q0[8] = acc[mi][ni][2]; q1[8] = acc[mi][ni][3];
            }
        }
    }
}

// ---------------------------------------------------------------------------
// Kernel 3: per-row top-12 -> softmax -> weighted gather of h
// ---------------------------------------------------------------------------
__global__ __launch_bounds__(256) void topk_kernel(const float* __restrict__ h,
                                                   float* __restrict__ out) {
    int row = blockIdx.x;
    int tid = threadIdx.x;
    const float* sim = g_sim + (size_t)row * NROWS;

    float v[TOPK]; int ix[TOPK];
    #pragma unroll
    for (int k = 0; k < TOPK; k++) { v[k] = -INFINITY; ix[k] = 0x7FFFFFFF; }

    #pragma unroll
    for (int t = 0; t < 8; t++) {
        int base4 = t * 256 + tid;
        float4 q = reinterpret_cast<const float4*>(sim)[base4];
        int j0 = base4 * 4;
        float qq[4] = {q.x, q.y, q.z, q.w};
        #pragma unroll
        for (int e = 0; e < 4; e++) {
            float val = qq[e];
            if (val > v[TOPK - 1]) {
                int p = TOPK - 1;
                #pragma unroll
                for (int s = TOPK - 1; s > 0; s--) {
                    if (v[s - 1] < val) { v[s] = v[s - 1]; ix[s] = ix[s - 1]; p = s - 1; }
                }
                v[p] = val; ix[p] = j0 + e;
            }
        }
    }

    __shared__ float sV[256][TOPK];
    __shared__ int   sI[256][TOPK];
    #pragma unroll
    for (int k = 0; k < TOPK; k++) { sV[tid][k] = v[k]; sI[tid][k] = ix[k]; }

    for (int stride = 128; stride > 0; stride >>= 1) {
        __syncthreads();
        if (tid < stride) {
            float mv[TOPK]; int mi[TOPK];
            int a = 0, b = 0;
            #pragma unroll
            for (int k = 0; k < TOPK; k++) {
                float va = sV[tid][a], vb = sV[tid + stride][b];
                int   ia = sI[tid][a], ib = sI[tid + stride][b];
                bool takeA = (va > vb) || (va == vb && ia < ib);
                if (takeA) { mv[k] = va; mi[k] = ia; a++; }
                else       { mv[k] = vb; mi[k] = ib; b++; }
            }
            #pragma unroll
            for (int k = 0; k < TOPK; k++) { sV[tid][k] = mv[k]; sI[tid][k] = mi[k]; }
        }
    }
    __syncthreads();

    __shared__ float sBeta[TOPK];
    __shared__ int   sIdx[TOPK];
    if (tid == 0) {
        float m = sV[0][0];
        float e[TOPK], sum = 0.0f;
        #pragma unroll
        for (int k = 0; k < TOPK; k++) { e[k] = expf(THETA * (sV[0][k] - m)); sum += e[k]; }
        float inv = 1.0f / sum;
        #pragma unroll
        for (int k = 0; k < TOPK; k++) { sBeta[k] = e[k] * inv; sIdx[k] = sI[0][k]; }
    }
    __syncthreads();

    float beta[TOPK]; const float* hp[TOPK];
    #pragma unroll
    for (int k = 0; k < TOPK; k++) { beta[k] = sBeta[k]; hp[k] = h + (size_t)sIdx[k] * DIM; }

    #pragma unroll
    for (int d = tid; d < DIM; d += 256) {
        float acc = 0.0f;
        #pragma unroll
        for (int k = 0; k < TOPK; k++) acc += beta[k] * hp[k][d];
        out[(size_t)row * DIM + d] = acc;
    }
}

// ---------------------------------------------------------------------------
extern "C" void kernel_launch(void* const* d_in, const int* in_sizes, int n_in,
                              void* d_out, int out_size) {
    const float* h = (const float*)d_in[0];
    float* out = (float*)d_out;

    cudaFuncSetAttribute(gemm_kernel, cudaFuncAttributeMaxDynamicSharedMemorySize, GSMEM);

    norm_kernel<<<NROWS, 256>>>(h);
    gemm_kernel<<<dim3(NROWS / 128, NROWS / 128), 256, GSMEM>>>();
    topk_kernel<<<NROWS, 256>>>(h, out);
}